// round 1
// baseline (speedup 1.0000x reference)
#include <cuda_runtime.h>
#include <cuda_bf16.h>

// 2-level 2D Haar DWT, fully fused.
// Input:  x (32,3,512,512) fp32 = 96 BC-planes of 512x512.
// Output: a2|h2|v2|d2 (96,128,128 each) then h1|v1|d1 (96,256,256 each),
//         concatenated flat in d_out (25,165,824 floats total).
//
// Per 2x2 input block (s00 s01 / s10 s11), pywt 'haar' dwt2 gives:
//   cA=(s00+s01+s10+s11)/2, cH=(s00+s01-s10-s11)/2,
//   cV=(s00-s01+s10-s11)/2, cD=(s00-s01-s10+s11)/2
// Level 2 applies the same transform to the cA1 field.
//
// One thread owns a 4x4 input tile -> 2x2 of each level-1 subband and
// 1 value of each level-2 subband. 16 floats in / 16 floats out.

#define IN_H   512
#define IN_W   512
#define L1_W   256
#define L2_W   128
#define PLANES 96                       // B*C = 32*3

#define N2 (PLANES * L2_W * L2_W)       // 1,572,864 per level-2 subband
#define N1 (PLANES * L1_W * L1_W)       // 6,291,456 per level-1 subband

// output section offsets (floats)
#define OFF_A2 ((size_t)0)
#define OFF_H2 ((size_t)N2)
#define OFF_V2 ((size_t)2 * N2)
#define OFF_D2 ((size_t)3 * N2)
#define OFF_H1 ((size_t)4 * N2)
#define OFF_V1 ((size_t)4 * N2 + (size_t)N1)
#define OFF_D1 ((size_t)4 * N2 + (size_t)2 * N1)

__device__ __forceinline__ void haar4(float s00, float s01, float s10, float s11,
                                      float& a, float& h, float& v, float& d) {
    float st = s00 + s01;   // sum  top row
    float dt = s00 - s01;   // diff top row
    float sb = s10 + s11;   // sum  bottom row
    float db = s10 - s11;   // diff bottom row
    a = (st + sb) * 0.5f;
    h = (st - sb) * 0.5f;
    v = (dt + db) * 0.5f;
    d = (dt - db) * 0.5f;
}

__global__ __launch_bounds__(256)
void haar2_fused_kernel(const float* __restrict__ x, float* __restrict__ out) {
    const int j  = blockIdx.x * 32 + threadIdx.x;   // 0..127 (level-2 col)
    const int i  = blockIdx.y * 8  + threadIdx.y;   // 0..127 (level-2 row)
    const int bc = blockIdx.z;                      // 0..95

    // ---- load 4x4 input tile as 4 x float4 (rows 4i..4i+3, cols 4j..4j+3) ----
    const float4* p = reinterpret_cast<const float4*>(
        x + (size_t)bc * (IN_H * IN_W) + (size_t)(4 * i) * IN_W) + j;
    const float4 r0 = p[0 * (IN_W / 4)];
    const float4 r1 = p[1 * (IN_W / 4)];
    const float4 r2 = p[2 * (IN_W / 4)];
    const float4 r3 = p[3 * (IN_W / 4)];

    // ---- level 1: four 2x2 blocks ----
    float a00, h00, v00, d00;  haar4(r0.x, r0.y, r1.x, r1.y, a00, h00, v00, d00);
    float a01, h01, v01, d01;  haar4(r0.z, r0.w, r1.z, r1.w, a01, h01, v01, d01);
    float a10, h10, v10, d10;  haar4(r2.x, r2.y, r3.x, r3.y, a10, h10, v10, d10);
    float a11, h11, v11, d11;  haar4(r2.z, r2.w, r3.z, r3.w, a11, h11, v11, d11);

    // ---- level 2 from the cA1 quad ----
    float a2, h2, v2, d2;      haar4(a00, a01, a10, a11, a2, h2, v2, d2);

    // ---- store level-1 details as float2 (rows 2i, 2i+1; cols 2j,2j+1) ----
    const size_t l1_plane = (size_t)bc * (L1_W * L1_W);
    const size_t l1r0 = l1_plane + (size_t)(2 * i) * L1_W;
    const size_t l1r1 = l1r0 + L1_W;

    reinterpret_cast<float2*>(out + OFF_H1 + l1r0)[j] = make_float2(h00, h01);
    reinterpret_cast<float2*>(out + OFF_H1 + l1r1)[j] = make_float2(h10, h11);
    reinterpret_cast<float2*>(out + OFF_V1 + l1r0)[j] = make_float2(v00, v01);
    reinterpret_cast<float2*>(out + OFF_V1 + l1r1)[j] = make_float2(v10, v11);
    reinterpret_cast<float2*>(out + OFF_D1 + l1r0)[j] = make_float2(d00, d01);
    reinterpret_cast<float2*>(out + OFF_D1 + l1r1)[j] = make_float2(d10, d11);

    // ---- store level-2 subbands (1 float each) ----
    const size_t l2 = (size_t)bc * (L2_W * L2_W) + (size_t)i * L2_W + j;
    out[OFF_A2 + l2] = a2;
    out[OFF_H2 + l2] = h2;
    out[OFF_V2 + l2] = v2;
    out[OFF_D2 + l2] = d2;
}

extern "C" void kernel_launch(void* const* d_in, const int* in_sizes, int n_in,
                              void* d_out, int out_size) {
    const float* x = (const float*)d_in[0];
    float* out     = (float*)d_out;
    dim3 block(32, 8, 1);
    dim3 grid(L2_W / 32, L2_W / 8, PLANES);   // (4, 16, 96)
    haar2_fused_kernel<<<grid, block>>>(x, out);
}

// round 3
// speedup vs baseline: 1.0230x; 1.0230x over previous
#include <cuda_runtime.h>
#include <cuda_bf16.h>

// 2-level 2D Haar DWT, fully fused, wide-tile version.
// Input:  x (32,3,512,512) fp32 = 96 BC-planes of 512x512.
// Output: a2|h2|v2|d2 (96,128,128 each) then h1|v1|d1 (96,256,256 each),
//         concatenated flat in d_out.
//
// One thread owns a 4-row x 8-col input tile:
//   -> 2x4 of each level-1 detail subband (stored as 2x STG.128 each)
//   -> 1x2 of each level-2 subband        (stored as STG.64 each)
// 32 floats in / 32 floats out per thread. Streaming cache hints (.cs)
// on both loads and stores since every byte is touched exactly once.

#define IN_H   512
#define IN_W   512
#define L1_W   256
#define L2_W   128
#define PLANES 96                       // B*C = 32*3

#define N2 (PLANES * L2_W * L2_W)       // elems per level-2 subband
#define N1 (PLANES * L1_W * L1_W)       // elems per level-1 subband

#define OFF_A2 ((size_t)0)
#define OFF_H2 ((size_t)N2)
#define OFF_V2 ((size_t)2 * N2)
#define OFF_D2 ((size_t)3 * N2)
#define OFF_H1 ((size_t)4 * N2)
#define OFF_V1 ((size_t)4 * N2 + (size_t)N1)
#define OFF_D1 ((size_t)4 * N2 + (size_t)2 * N1)

__device__ __forceinline__ void haar4(float s00, float s01, float s10, float s11,
                                      float& a, float& h, float& v, float& d) {
    float st = s00 + s01;
    float dt = s00 - s01;
    float sb = s10 + s11;
    float db = s10 - s11;
    a = (st + sb) * 0.5f;
    h = (st - sb) * 0.5f;
    v = (dt + db) * 0.5f;
    d = (dt - db) * 0.5f;
}

__global__ __launch_bounds__(256)
void haar2_fused_wide_kernel(const float* __restrict__ x, float* __restrict__ out) {
    const int jj = blockIdx.x * 32 + threadIdx.x;   // 0..63  : pair of level-2 cols
    const int i  = blockIdx.y * 8  + threadIdx.y;   // 0..127 : level-2 row
    const int bc = blockIdx.z;                      // 0..95

    // ---- load 4 rows x 8 cols as 8 x float4 (cols 8*jj .. 8*jj+7) ----
    const float4* p = reinterpret_cast<const float4*>(
        x + (size_t)bc * (IN_H * IN_W) + (size_t)(4 * i) * IN_W) + 2 * jj;
    const int RW = IN_W / 4;            // 128 float4 per row
    const float4 r0a = __ldcs(p + 0 * RW);
    const float4 r0b = __ldcs(p + 0 * RW + 1);
    const float4 r1a = __ldcs(p + 1 * RW);
    const float4 r1b = __ldcs(p + 1 * RW + 1);
    const float4 r2a = __ldcs(p + 2 * RW);
    const float4 r2b = __ldcs(p + 2 * RW + 1);
    const float4 r3a = __ldcs(p + 3 * RW);
    const float4 r3b = __ldcs(p + 3 * RW + 1);

    // ---- level 1: eight 2x2 blocks (cols c0..c3 of the L1 grid) ----
    float a00,h00,v00,d00;  haar4(r0a.x, r0a.y, r1a.x, r1a.y, a00,h00,v00,d00);
    float a01,h01,v01,d01;  haar4(r0a.z, r0a.w, r1a.z, r1a.w, a01,h01,v01,d01);
    float a02,h02,v02,d02;  haar4(r0b.x, r0b.y, r1b.x, r1b.y, a02,h02,v02,d02);
    float a03,h03,v03,d03;  haar4(r0b.z, r0b.w, r1b.z, r1b.w, a03,h03,v03,d03);

    float a10,h10,v10,d10;  haar4(r2a.x, r2a.y, r3a.x, r3a.y, a10,h10,v10,d10);
    float a11,h11,v11,d11;  haar4(r2a.z, r2a.w, r3a.z, r3a.w, a11,h11,v11,d11);
    float a12,h12,v12,d12;  haar4(r2b.x, r2b.y, r3b.x, r3b.y, a12,h12,v12,d12);
    float a13,h13,v13,d13;  haar4(r2b.z, r2b.w, r3b.z, r3b.w, a13,h13,v13,d13);

    // ---- level 2 from the two cA1 quads ----
    float a2l,h2l,v2l,d2l;  haar4(a00, a01, a10, a11, a2l,h2l,v2l,d2l);
    float a2r,h2r,v2r,d2r;  haar4(a02, a03, a12, a13, a2r,h2r,v2r,d2r);

    // ---- store level-1 details: float4 per row (L1 cols 4*jj..4*jj+3) ----
    const size_t l1_plane = (size_t)bc * (L1_W * L1_W);
    float4* h1r0 = reinterpret_cast<float4*>(out + OFF_H1 + l1_plane + (size_t)(2 * i) * L1_W) + jj;
    float4* h1r1 = reinterpret_cast<float4*>(out + OFF_H1 + l1_plane + (size_t)(2 * i + 1) * L1_W) + jj;
    float4* v1r0 = reinterpret_cast<float4*>(out + OFF_V1 + l1_plane + (size_t)(2 * i) * L1_W) + jj;
    float4* v1r1 = reinterpret_cast<float4*>(out + OFF_V1 + l1_plane + (size_t)(2 * i + 1) * L1_W) + jj;
    float4* d1r0 = reinterpret_cast<float4*>(out + OFF_D1 + l1_plane + (size_t)(2 * i) * L1_W) + jj;
    float4* d1r1 = reinterpret_cast<float4*>(out + OFF_D1 + l1_plane + (size_t)(2 * i + 1) * L1_W) + jj;

    __stcs(h1r0, make_float4(h00, h01, h02, h03));
    __stcs(h1r1, make_float4(h10, h11, h12, h13));
    __stcs(v1r0, make_float4(v00, v01, v02, v03));
    __stcs(v1r1, make_float4(v10, v11, v12, v13));
    __stcs(d1r0, make_float4(d00, d01, d02, d03));
    __stcs(d1r1, make_float4(d10, d11, d12, d13));

    // ---- store level-2 subbands: float2 (L2 cols 2*jj, 2*jj+1) ----
    const size_t l2row = (size_t)bc * (L2_W * L2_W) + (size_t)i * L2_W;
    __stcs(reinterpret_cast<float2*>(out + OFF_A2 + l2row) + jj, make_float2(a2l, a2r));
    __stcs(reinterpret_cast<float2*>(out + OFF_H2 + l2row) + jj, make_float2(h2l, h2r));
    __stcs(reinterpret_cast<float2*>(out + OFF_V2 + l2row) + jj, make_float2(v2l, v2r));
    __stcs(reinterpret_cast<float2*>(out + OFF_D2 + l2row) + jj, make_float2(d2l, d2r));
}

extern "C" void kernel_launch(void* const* d_in, const int* in_sizes, int n_in,
                              void* d_out, int out_size) {
    const float* x = (const float*)d_in[0];
    float* out     = (float*)d_out;
    dim3 block(32, 8, 1);
    dim3 grid(2, 16, 96);               // jj: 64/32=2, i: 128/8=16, bc: 96
    haar2_fused_wide_kernel<<<grid, block>>>(x, out);
}